// round 15
// baseline (speedup 1.0000x reference)
#include <cuda_runtime.h>
#include <cuda_fp16.h>
#include <cuda_fp8.h>
#include <cstdint>

#define HH 96
#define WW 96
#define CC 21
#define NN 9216          // HH*WW
#define CP 24            // padded channel count
#define BROWS 48         // B operand rows: 24 hi + 24 lo (residual)

#define KT 128           // k-tile (fp8 elements = bytes)
#define RB 128           // rows per gemm block (4 warps x m32)
#define NTILES (NN / RB)      // 72 row tiles
#define KB_W 6656             // banded storage width (>= max window len 6272)
#define KSPLIT 3
#define NCONVB 42             // 21 channels x 2 y-halves
#define SA_BUF (RB * 128)     // 16384 B per stage
#define SB_BUF (BROWS * 128)  // 6144 B per stage

// ---------------- scratch (device globals; no allocation allowed) ----------------
__device__ uint8_t g_Kb[(size_t)NTILES * RB * KB_W];  // banded bilateral kernel, e4m3, ~61MB
__device__ __half  g_pT[CC * NN];           // probs planar [c][n], fp16 (conv path)
__device__ uint8_t g_pT8[BROWS * NN];       // probs e4m3 planar: rows 0-23 hi, 24-47 lo*64
__device__ float   g_S[CC * NN];            // spatial message, planar
__device__ float   g_Bp[KSPLIT][NN * CP];   // bilateral partials per k-split
__device__ float   g_tap[64];               // 60 FIR taps exp(-(t-29)^2/18), zero-padded
__device__ float   g_Ws[CC * CC];           // compat[k][c] * ws[c]
__device__ float   g_Wb[CC * CC];           // compat[k][c] * wb[c]
__device__ float   g_col[NN * 3];           // colors * 8 (= /theta_beta)

// banded window for a row tile (identical formula in build and gemm)
__device__ __forceinline__ void tile_window(int tile, int& jlo, int& jhi) {
    int rowBase = tile * RB;
    int ya = rowBase / WW;
    int yb = (rowBase + RB - 1) / WW;
    jlo = max(0, (ya - 30) * WW) & ~(KT - 1);
    jhi = min(NN, ((yb + 31) * WW + KT - 1) & ~(KT - 1));
}

// ---------------- async / ldmatrix helpers ----------------
#define CP_ASYNC16(dst, src) \
    asm volatile("cp.async.cg.shared.global [%0], [%1], 16;\n" :: "r"(dst), "l"(src))
#define CP_COMMIT() asm volatile("cp.async.commit_group;\n" ::: "memory")
#define CP_WAIT2()  asm volatile("cp.async.wait_group 2;\n" ::: "memory")
#define LDSM4(r0, r1, r2, r3, addr) \
    asm volatile("ldmatrix.sync.aligned.m8n8.x4.shared.b16 {%0,%1,%2,%3}, [%4];" \
                 : "=r"(r0), "=r"(r1), "=r"(r2), "=r"(r3) : "r"(addr))

__device__ __forceinline__ uint8_t to_e4m3(float f) {
    return (uint8_t)__nv_cvt_float_to_fp8(f, __NV_SATFINITE, __NV_E4M3);
}
__device__ __forceinline__ float from_e4m3(uint8_t s) {
    return __half2float(__nv_cvt_fp8_to_halfraw((__nv_fp8_storage_t)s, __NV_E4M3));
}

// ---------------- prep ----------------
__global__ void prep_kernel(const float* __restrict__ ref, const float* __restrict__ ws,
                            const float* __restrict__ wb, const float* __restrict__ cm) {
    int t = blockIdx.x * 256 + threadIdx.x;
    if (t < NN) {
        g_col[t * 3 + 0] = ref[t * 3 + 0] * 8.0f;
        g_col[t * 3 + 1] = ref[t * 3 + 1] * 8.0f;
        g_col[t * 3 + 2] = ref[t * 3 + 2] * 8.0f;
    }
    if (t < 64) {
        float d = (float)(t - 29);
        g_tap[t] = (t < 60) ? __expf(-0.5f * d * d / 9.0f) : 0.0f;  // theta_gamma = 3
    }
    if (t < CC * CC) {
        g_Ws[t] = cm[t] * ws[t % CC];
        g_Wb[t] = cm[t] * wb[t % CC];
    }
}

// ---------------- build banded bilateral kernel (fp8, once) ----------------
// exp(-0.5*d2) rounds to e4m3 zero when d2 > 13.86; skipping expf there is exact.
__global__ void build_k_kernel() {
    int tile = blockIdx.y >> 3;
    int i0 = tile * RB + (blockIdx.y & 7) * 16;
    int jlo, jhi;
    tile_window(tile, jlo, jhi);
    int kcol = (blockIdx.x * 128 + threadIdx.x) * 4;
    int j0 = jlo + kcol;
    if (j0 >= jhi) return;                     // padding beyond window: never read
    float yj = (float)(j0 / WW), xj = (float)(j0 % WW);  // quad within one row (WW%4==0)
    float cr[4], cg[4], cb[4];
#pragma unroll
    for (int t = 0; t < 4; t++) {
        cr[t] = g_col[(j0 + t) * 3 + 0];
        cg[t] = g_col[(j0 + t) * 3 + 1];
        cb[t] = g_col[(j0 + t) * 3 + 2];
    }
    uint8_t* dst0 = g_Kb + (size_t)i0 * KB_W + kcol;
#pragma unroll 2
    for (int t = 0; t < 16; t++) {
        int i = i0 + t;
        float yi = (float)(i / WW), xi = (float)(i % WW);
        float ri = g_col[i * 3 + 0], gi = g_col[i * 3 + 1], bi = g_col[i * 3 + 2];
        float dy = yi - yj;
        float d2v[4];
        bool nearv = false;
#pragma unroll
        for (int s = 0; s < 4; s++) {
            float dx = xi - (xj + (float)s);
            float d2 = (dy * dy + dx * dx) * (1.0f / 64.0f);
            float dr = ri - cr[s], dg = gi - cg[s], db = bi - cb[s];
            d2 += dr * dr + dg * dg + db * db;
            d2v[s] = d2;
            nearv |= (d2 < 13.86f);
        }
        uint32_t packed = 0;
        if (__ballot_sync(0xffffffffu, nearv)) {   // whole warp far -> skip all MUFU
            if (nearv) {
#pragma unroll
                for (int s = 0; s < 4; s++) {
                    float e = (d2v[s] < 13.86f) ? __expf(-0.5f * d2v[s]) : 0.0f;
                    packed |= (uint32_t)to_e4m3(e) << (8 * s);
                }
            }
        }
        *reinterpret_cast<uint32_t*>(dst0 + (size_t)t * KB_W) = packed;
    }
}

// ---------------- prob emission (shared by softmax0 and update) ----------------
__device__ __forceinline__ void emit_probs(const float* v, int n) {
    float mx = -1e30f;
#pragma unroll
    for (int c = 0; c < CC; c++) mx = fmaxf(mx, v[c]);
    float s = 0.0f;
    float e[CC];
#pragma unroll
    for (int c = 0; c < CC; c++) { e[c] = __expf(v[c] - mx); s += e[c]; }
    float inv = 1.0f / s;
#pragma unroll
    for (int c = 0; c < CC; c++) {
        float p = e[c] * inv;
        g_pT[c * NN + n] = __float2half_rn(p);
        uint8_t hi = to_e4m3(p);
        float res = 64.0f * (p - from_e4m3(hi));
        g_pT8[c * NN + n] = hi;
        g_pT8[(CP + c) * NN + n] = to_e4m3(res);
    }
#pragma unroll
    for (int c = CC; c < CP; c++) {
        g_pT8[c * NN + n] = 0;
        g_pT8[(CP + c) * NN + n] = 0;
    }
}

__global__ void softmax0_kernel(const float* __restrict__ u) {
    int n = blockIdx.x * 128 + threadIdx.x;
    float v[CC];
#pragma unroll
    for (int c = 0; c < CC; c++) v[c] = u[n * CC + c];
    emit_probs(v, n);
}

// ---------------- fp8 GEMM + fused spatial conv (heterogeneous blocks) ----------------
// Blocks 0..41: separable 60-tap Gaussian conv (channel = b/2, y-half = b&1), all in smem.
// Blocks 42..: banded fp8 GEMM, k-window split KSPLIT ways.
__device__ __forceinline__ void mma_fp8(float* d, uint32_t a0, uint32_t a1, uint32_t a2,
                                        uint32_t a3, uint32_t b0, uint32_t b1) {
    asm volatile(
        "mma.sync.aligned.m16n8k32.row.col.f32.e4m3.e4m3.f32 "
        "{%0,%1,%2,%3},{%4,%5,%6,%7},{%8,%9},{%0,%1,%2,%3};\n"
        : "+f"(d[0]), "+f"(d[1]), "+f"(d[2]), "+f"(d[3])
        : "r"(a0), "r"(a1), "r"(a2), "r"(a3), "r"(b0), "r"(b1));
}

__global__ void __launch_bounds__(128, 2) iter_kernel() {
    __shared__ __align__(16) uint8_t sA[4 * SA_BUF];   // 65536 B (union: gemm stages / conv bufs)
    __shared__ __align__(16) uint8_t sB[4 * SB_BUF];   // 24576 B (union: gemm stages / conv taps)
    int tid = threadIdx.x;

    if (blockIdx.x < NCONVB) {
        // ---------------- conv block: one (channel, y-half) ----------------
        int cb = blockIdx.x;
        int c = cb >> 1, half = cb & 1;
        float* bufP = reinterpret_cast<float*>(sA);            // probs rows [rlo,rhi), 78x96 max
        float* bufX = reinterpret_cast<float*>(sA + 30720);    // xconv rows, 78x96 max
        float* tp   = reinterpret_cast<float*>(sB);            // 64 taps
        if (tid < 64) tp[tid] = g_tap[tid];
        int y0 = half * 48;
        int rlo = max(0, y0 - 29), rhi = min(HH, y0 + 78);
        int nrows = rhi - rlo;
        for (int t = tid; t < nrows * WW; t += 128)
            bufP[t] = __half2float(g_pT[c * NN + rlo * WW + t]);
        __syncthreads();
        for (int idx = tid; idx < nrows * WW; idx += 128) {
            int r = idx / WW, x = idx - r * WW;
            float a0 = 0.f, a1 = 0.f;
#pragma unroll
            for (int t = 0; t < 60; t += 2) {
                int x0 = x + t - 29, x1 = x0 + 1;
                if (x0 >= 0 && x0 < WW) a0 += tp[t] * bufP[r * WW + x0];
                if (x1 >= 0 && x1 < WW) a1 += tp[t + 1] * bufP[r * WW + x1];
            }
            bufX[idx] = a0 + a1;
        }
        __syncthreads();
        for (int idx = tid; idx < 48 * WW; idx += 128) {
            int yr = idx / WW, x = idx - yr * WW;
            int y = y0 + yr;
            float a0 = 0.f, a1 = 0.f;
#pragma unroll
            for (int t = 0; t < 60; t += 2) {
                int y0p = y - 29 + t, y1p = y0p + 1;
                if (y0p >= rlo && y0p < rhi) a0 += tp[t] * bufX[(y0p - rlo) * WW + x];
                if (y1p >= rlo && y1p < rhi) a1 += tp[t + 1] * bufX[(y1p - rlo) * WW + x];
            }
            g_S[c * NN + y * WW + x] = a0 + a1;
        }
        return;
    }

    // ---------------- gemm block ----------------
    int g = blockIdx.x - NCONVB;
    int tile = g / KSPLIT, ks = g - tile * KSPLIT;
    int warp = tid >> 5, lane = tid & 31;
    int grp = lane >> 2, tig = lane & 3;
    int rowBase = tile * RB;

    int jlo, jhi;
    tile_window(tile, jlo, jhi);
    int len = jhi - jlo;
    int chunk = ((len / KSPLIT + KT - 1) / KT) * KT;
    int kstartRel = ks * chunk;
    int kendRel = min(len, kstartRel + chunk);
    int NST = (kendRel > kstartRel) ? (kendRel - kstartRel) / KT : 0;

    const uint8_t* Arow0 = g_Kb + (size_t)rowBase * KB_W + kstartRel;
    const uint8_t* Bbase = g_pT8 + jlo + kstartRel;

    uint32_t sA_u = (uint32_t)__cvta_generic_to_shared(&sA[0]);
    uint32_t sB_u = (uint32_t)__cvta_generic_to_shared(&sB[0]);

    auto prefetch = [&](int s, int buf) {
        if (s >= NST) return;
        size_t kbase = (size_t)s * KT;
#pragma unroll
        for (int i = 0; i < 8; i++) {            // 1024 chunks of 16B for A (128 rows)
            int chunkid = tid + i * 128;
            int r = chunkid >> 3, cix = chunkid & 7;
            const uint8_t* src = Arow0 + (size_t)r * KB_W + kbase + cix * 16;
            uint32_t dst = sA_u + buf * SA_BUF + r * 128 + ((cix ^ (r & 7)) << 4);
            CP_ASYNC16(dst, src);
        }
#pragma unroll
        for (int i = 0; i < 3; i++) {            // 384 chunks for B (48 rows)
            int chunkid = tid + i * 128;
            int r = chunkid >> 3, cix = chunkid & 7;
            const uint8_t* src = Bbase + (size_t)r * NN + kbase + cix * 16;
            uint32_t dst = sB_u + buf * SB_BUF + r * 128 + ((cix ^ (r & 7)) << 4);
            CP_ASYNC16(dst, src);
        }
    };

    float d[2][6][4];
#pragma unroll
    for (int m = 0; m < 2; m++)
#pragma unroll
        for (int i = 0; i < 6; i++)
#pragma unroll
            for (int j = 0; j < 4; j++) d[m][i][j] = 0.0f;

    prefetch(0, 0); CP_COMMIT();
    prefetch(1, 1); CP_COMMIT();
    prefetch(2, 2); CP_COMMIT();

    // ---- ldmatrix address setup (loop-invariant) ----
    int l7 = lane & 7;
    int aHalf = lane >> 4;
    int bHalf = (lane >> 3) & 1;
    uint32_t aBase[2];
#pragma unroll
    for (int m = 0; m < 2; m++) {
        int aRow = warp * 32 + m * 16 + ((lane >> 3) & 1) * 8 + l7;
        aBase[m] = sA_u + (uint32_t)aRow * 128;
    }
    uint32_t bBase[3];
#pragma unroll
    for (int p = 0; p < 3; p++)
        bBase[p] = sB_u + (uint32_t)(((2 * p + (lane >> 4)) * 8 + l7) * 128);
    int offA[4], offB[4];
#pragma unroll
    for (int kk = 0; kk < 4; kk++) {
        offA[kk] = (((2 * kk + aHalf) ^ l7) << 4);
        offB[kk] = (((2 * kk + bHalf) ^ l7) << 4);
    }

    int buf = 0;
    for (int s = 0; s < NST; s++) {
        CP_WAIT2();
        __syncthreads();
        prefetch(s + 3, (s + 3) & 3);
        CP_COMMIT();
        uint32_t A0 = aBase[0] + buf * SA_BUF;
        uint32_t A1 = aBase[1] + buf * SA_BUF;
        uint32_t B0 = bBase[0] + buf * SB_BUF;
        uint32_t B1 = bBase[1] + buf * SB_BUF;
        uint32_t B2 = bBase[2] + buf * SB_BUF;
        buf = (buf + 1) & 3;
#pragma unroll
        for (int kk = 0; kk < 4; kk++) {
            uint32_t a00, a01, a02, a03, a10, a11, a12, a13;
            LDSM4(a00, a01, a02, a03, A0 + offA[kk]);
            LDSM4(a10, a11, a12, a13, A1 + offA[kk]);
            uint32_t b00, b01, b10, b11;
            LDSM4(b00, b01, b10, b11, B0 + offB[kk]);
            uint32_t b20, b21, b30, b31;
            LDSM4(b20, b21, b30, b31, B1 + offB[kk]);
            uint32_t b40, b41, b50, b51;
            LDSM4(b40, b41, b50, b51, B2 + offB[kk]);
            mma_fp8(d[0][0], a00, a01, a02, a03, b00, b01);
            mma_fp8(d[0][1], a00, a01, a02, a03, b10, b11);
            mma_fp8(d[0][2], a00, a01, a02, a03, b20, b21);
            mma_fp8(d[0][3], a00, a01, a02, a03, b30, b31);
            mma_fp8(d[0][4], a00, a01, a02, a03, b40, b41);
            mma_fp8(d[0][5], a00, a01, a02, a03, b50, b51);
            mma_fp8(d[1][0], a10, a11, a12, a13, b00, b01);
            mma_fp8(d[1][1], a10, a11, a12, a13, b10, b11);
            mma_fp8(d[1][2], a10, a11, a12, a13, b20, b21);
            mma_fp8(d[1][3], a10, a11, a12, a13, b30, b31);
            mma_fp8(d[1][4], a10, a11, a12, a13, b40, b41);
            mma_fp8(d[1][5], a10, a11, a12, a13, b50, b51);
        }
    }

    float* outp = g_Bp[ks];
#pragma unroll
    for (int m = 0; m < 2; m++) {
        int row0 = rowBase + warp * 32 + m * 16 + grp;
#pragma unroll
        for (int nt = 0; nt < 3; nt++) {   // combine hi + lo/64
            int col = nt * 8 + 2 * tig;
            float v00 = d[m][nt][0] + d[m][nt + 3][0] * (1.0f / 64.0f);
            float v01 = d[m][nt][1] + d[m][nt + 3][1] * (1.0f / 64.0f);
            float v10 = d[m][nt][2] + d[m][nt + 3][2] * (1.0f / 64.0f);
            float v11 = d[m][nt][3] + d[m][nt + 3][3] * (1.0f / 64.0f);
            *reinterpret_cast<float2*>(&outp[(size_t)row0 * CP + col]) = make_float2(v00, v01);
            *reinterpret_cast<float2*>(&outp[(size_t)(row0 + 8) * CP + col]) = make_float2(v10, v11);
        }
    }
}

// ---------------- fused update + softmax: q = u - S@Ws^T - B@Wb^T, then probs ----------------
__global__ void update_kernel(const float* __restrict__ u, float* __restrict__ outp, int last) {
    __shared__ float su[64 * CC];
    __shared__ float sws[CC * CC], swb[CC * CC];
    int tid = threadIdx.x;
    for (int t = tid; t < CC * CC; t += 64) { sws[t] = g_Ws[t]; swb[t] = g_Wb[t]; }
    int base = blockIdx.x * 64 * CC;
    for (int t = tid; t < 64 * CC; t += 64) su[t] = u[base + t];
    __syncthreads();
    int n = blockIdx.x * 64 + tid;

    float sv[CC], bv[CP];
#pragma unroll
    for (int c = 0; c < CC; c++) sv[c] = g_S[c * NN + n];
#pragma unroll
    for (int q4 = 0; q4 < 6; q4++) {
        float ax = 0.f, ay = 0.f, az = 0.f, aw = 0.f;
#pragma unroll
        for (int p = 0; p < KSPLIT; p++) {
            float4 t = *reinterpret_cast<const float4*>(&g_Bp[p][(size_t)n * CP + q4 * 4]);
            ax += t.x; ay += t.y; az += t.z; aw += t.w;
        }
        bv[q4 * 4 + 0] = ax; bv[q4 * 4 + 1] = ay;
        bv[q4 * 4 + 2] = az; bv[q4 * 4 + 3] = aw;
    }

    float qn[CC];
#pragma unroll
    for (int k = 0; k < CC; k++) {
        float acc = 0.0f;
#pragma unroll
        for (int c = 0; c < CC; c++)
            acc += sws[k * CC + c] * sv[c] + swb[k * CC + c] * bv[c];
        qn[k] = su[tid * CC + k] - acc;
    }

    if (last) {
#pragma unroll
        for (int k = 0; k < CC; k++) outp[n * CC + k] = qn[k];
    } else {
        emit_probs(qn, n);
    }
}

// ---------------- launch: build || softmax0, then 5 x (iter_kernel -> update), one stream ----
extern "C" void kernel_launch(void* const* d_in, const int* in_sizes, int n_in,
                              void* d_out, int out_size) {
    const float* u   = (const float*)d_in[0];
    const float* ref = (const float*)d_in[1];
    const float* ws  = (const float*)d_in[2];
    const float* wb  = (const float*)d_in[3];
    const float* cm  = (const float*)d_in[4];
    float* out = (float*)d_out;

    static cudaStream_t s2 = nullptr;
    static cudaEvent_t eFork = nullptr, eEmit = nullptr;
    if (s2 == nullptr) {
        cudaStreamCreateWithFlags(&s2, cudaStreamNonBlocking);
        cudaEventCreateWithFlags(&eFork, cudaEventDisableTiming);
        cudaEventCreateWithFlags(&eEmit, cudaEventDisableTiming);
    }

    // fork side stream off the main (legacy) stream
    cudaEventRecord(eFork, 0);
    cudaStreamWaitEvent(s2, eFork, 0);

    // main: prep -> build_K. side: softmax0 (needs only u).
    prep_kernel<<<36, 256>>>(ref, ws, wb, cm);
    build_k_kernel<<<dim3(13, 576), 128>>>();

    softmax0_kernel<<<72, 128, 0, s2>>>(u);
    cudaEventRecord(eEmit, s2);
    cudaStreamWaitEvent(0, eEmit, 0);   // main waits for iteration-0 probs

    for (int it = 0; it < 5; it++) {
        iter_kernel<<<NCONVB + NTILES * KSPLIT, 128>>>();
        update_kernel<<<144, 64>>>(u, out, it == 4 ? 1 : 0);
    }
}

// round 16
// speedup vs baseline: 1.4078x; 1.4078x over previous
#include <cuda_runtime.h>
#include <cuda_fp16.h>
#include <cuda_fp8.h>
#include <cstdint>

#define HH 96
#define WW 96
#define CC 21
#define NN 9216          // HH*WW
#define CP 24            // padded channel count
#define BROWS 48         // B operand rows: 24 hi + 24 lo (residual)

#define KT 128           // k-tile (fp8 elements = bytes)
#define RB 128           // rows per gemm block (4 warps x m32)
#define NTILES (NN / RB)      // 72 row tiles
#define KB_W 6144             // banded storage width (max window: 61 rows + align = 6144)
#define KSPLIT 4
#define SA_BUF (RB * 128)     // 16384 B per stage
#define SB_BUF (BROWS * 128)  // 6144 B per stage

#define TMP_ROWS 160          // 96 rows + 29 top halo + 35 bottom pad (zeroed)
#define TMP_PLANE (TMP_ROWS * WW)

// ---------------- scratch (device globals; no allocation allowed) ----------------
__device__ uint8_t g_Kb[(size_t)NTILES * RB * KB_W];  // banded bilateral kernel, e4m3, ~57MB
__device__ __half  g_pT[CC * NN];           // probs planar [c][n], fp16 (conv path)
__device__ uint8_t g_pT8[BROWS * NN];       // probs e4m3 planar: rows 0-23 hi, 24-47 lo*64
__device__ float   g_tmp2[CC * TMP_PLANE];  // conv intermediate, y-haloed planar
__device__ float   g_S[CC * NN];            // spatial message, planar
__device__ float   g_Bp[KSPLIT][NN * CP];   // bilateral partials per k-split
__device__ float   g_tap[64];               // 60 FIR taps exp(-(t-29)^2/18), zero-padded
__device__ float   g_Ws[CC * CC];           // compat[k][c] * ws[c]
__device__ float   g_Wb[CC * CC];           // compat[k][c] * wb[c]

// banded window for a row tile (identical formula in build and gemm)
// K[i][j] is exactly 0 in e4m3 when |y_i - y_j| >= 30, so the window is |dy| <= 29.
__device__ __forceinline__ void tile_window(int tile, int& jlo, int& jhi) {
    int rowBase = tile * RB;
    int ya = rowBase / WW;
    int yb = (rowBase + RB - 1) / WW;
    jlo = max(0, (ya - 29) * WW) & ~(KT - 1);
    jhi = min(NN, ((yb + 30) * WW + KT - 1) & ~(KT - 1));
}

// ---------------- async / ldmatrix helpers ----------------
#define CP_ASYNC16(dst, src) \
    asm volatile("cp.async.cg.shared.global [%0], [%1], 16;\n" :: "r"(dst), "l"(src))
#define CP_COMMIT() asm volatile("cp.async.commit_group;\n" ::: "memory")
#define CP_WAIT2()  asm volatile("cp.async.wait_group 2;\n" ::: "memory")
#define LDSM4(r0, r1, r2, r3, addr) \
    asm volatile("ldmatrix.sync.aligned.m8n8.x4.shared.b16 {%0,%1,%2,%3}, [%4];" \
                 : "=r"(r0), "=r"(r1), "=r"(r2), "=r"(r3) : "r"(addr))

__device__ __forceinline__ uint8_t to_e4m3(float f) {
    return (uint8_t)__nv_cvt_float_to_fp8(f, __NV_SATFINITE, __NV_E4M3);
}
__device__ __forceinline__ float from_e4m3(uint8_t s) {
    return __half2float(__nv_cvt_fp8_to_halfraw((__nv_fp8_storage_t)s, __NV_E4M3));
}

// ---------------- prep (side stream; NOT on the critical path) ----------------
__global__ void prep_kernel(const float* __restrict__ ws,
                            const float* __restrict__ wb, const float* __restrict__ cm) {
    int t = blockIdx.x * 256 + threadIdx.x;
    if (t < 64) {
        float d = (float)(t - 29);
        g_tap[t] = (t < 60) ? __expf(-0.5f * d * d / 9.0f) : 0.0f;  // theta_gamma = 3
    }
    if (t < CC * CC) {
        g_Ws[t] = cm[t] * ws[t % CC];
        g_Wb[t] = cm[t] * wb[t % CC];
    }
    // zero the haloed tmp planes once; interior is overwritten every iteration
    for (int i = t; i < CC * TMP_PLANE; i += 36 * 256) g_tmp2[i] = 0.0f;
}

// ---------------- build banded bilateral kernel (fp8, once; reads ref directly) ----------------
// exp(-0.5*d2) rounds to e4m3 zero when d2 > 13.86; skipping expf there is exact.
__global__ void build_k_kernel(const float* __restrict__ ref) {
    int tile = blockIdx.y >> 3;
    int i0 = tile * RB + (blockIdx.y & 7) * 16;
    int jlo, jhi;
    tile_window(tile, jlo, jhi);
    int kcol = (blockIdx.x * 128 + threadIdx.x) * 4;
    int j0 = jlo + kcol;
    if (j0 >= jhi) return;                     // padding beyond window: never read
    float yj = (float)(j0 / WW), xj = (float)(j0 % WW);  // quad within one row (WW%4==0)
    float cr[4], cg[4], cb[4];
#pragma unroll
    for (int t = 0; t < 4; t++) {
        cr[t] = ref[(j0 + t) * 3 + 0] * 8.0f;
        cg[t] = ref[(j0 + t) * 3 + 1] * 8.0f;
        cb[t] = ref[(j0 + t) * 3 + 2] * 8.0f;
    }
    uint8_t* dst0 = g_Kb + (size_t)i0 * KB_W + kcol;
#pragma unroll 2
    for (int t = 0; t < 16; t++) {
        int i = i0 + t;
        float yi = (float)(i / WW), xi = (float)(i % WW);
        float ri = ref[i * 3 + 0] * 8.0f, gi = ref[i * 3 + 1] * 8.0f, bi = ref[i * 3 + 2] * 8.0f;
        float dy = yi - yj;
        float d2v[4];
        bool nearv = false;
#pragma unroll
        for (int s = 0; s < 4; s++) {
            float dx = xi - (xj + (float)s);
            float d2 = (dy * dy + dx * dx) * (1.0f / 64.0f);
            float dr = ri - cr[s], dg = gi - cg[s], db = bi - cb[s];
            d2 += dr * dr + dg * dg + db * db;
            d2v[s] = d2;
            nearv |= (d2 < 13.86f);
        }
        uint32_t packed = 0;
        if (__ballot_sync(0xffffffffu, nearv)) {   // whole warp far -> skip all MUFU
            if (nearv) {
#pragma unroll
                for (int s = 0; s < 4; s++) {
                    float e = (d2v[s] < 13.86f) ? __expf(-0.5f * d2v[s]) : 0.0f;
                    packed |= (uint32_t)to_e4m3(e) << (8 * s);
                }
            }
        }
        *reinterpret_cast<uint32_t*>(dst0 + (size_t)t * KB_W) = packed;
    }
}

// ---------------- prob emission (shared by softmax0 and update) ----------------
__device__ __forceinline__ void emit_probs(const float* v, int n) {
    float mx = -1e30f;
#pragma unroll
    for (int c = 0; c < CC; c++) mx = fmaxf(mx, v[c]);
    float s = 0.0f;
    float e[CC];
#pragma unroll
    for (int c = 0; c < CC; c++) { e[c] = __expf(v[c] - mx); s += e[c]; }
    float inv = 1.0f / s;
#pragma unroll
    for (int c = 0; c < CC; c++) {
        float p = e[c] * inv;
        g_pT[c * NN + n] = __float2half_rn(p);
        uint8_t hi = to_e4m3(p);
        float res = 64.0f * (p - from_e4m3(hi));
        g_pT8[c * NN + n] = hi;
        g_pT8[(CP + c) * NN + n] = to_e4m3(res);
    }
#pragma unroll
    for (int c = CC; c < CP; c++) {
        g_pT8[c * NN + n] = 0;
        g_pT8[(CP + c) * NN + n] = 0;
    }
}

__global__ void softmax0_kernel(const float* __restrict__ u) {
    int n = blockIdx.x * 128 + threadIdx.x;
    float v[CC];
#pragma unroll
    for (int c = 0; c < CC; c++) v[c] = u[n * CC + c];
    emit_probs(v, n);
}

// ---------------- separable spatial filtering: 60-tap Gaussian FIR ----------------
// G(d) < 2e-22 for |d| >= 30: dropped terms are below 1 ulp of the fp32 sums.
__global__ void conv_x_kernel() {   // grid = (96 y, 7 cg), block = 288 (3 ch * 96 x)
    __shared__ float sp[3][160];    // 29 zeros | 96 probs | 31 zeros
    __shared__ float tap[64];
    int tid = threadIdx.x;
    int sub = tid / 96, x = tid % 96;
    int y = blockIdx.x;
    int c = blockIdx.y * 3 + sub;
    if (tid < 64) tap[tid] = g_tap[tid];
    if (x < 29) sp[sub][x] = 0.0f;
    if (x >= 65) sp[sub][x + 60] = 0.0f;      // covers [125,156)
    sp[sub][x + 29] = __half2float(g_pT[c * NN + y * WW + x]);
    __syncthreads();
    float a0 = 0.f, a1 = 0.f, a2 = 0.f, a3 = 0.f;
#pragma unroll
    for (int t = 0; t < 60; t += 4) {
        a0 += tap[t + 0] * sp[sub][x + t + 0];
        a1 += tap[t + 1] * sp[sub][x + t + 1];
        a2 += tap[t + 2] * sp[sub][x + t + 2];
        a3 += tap[t + 3] * sp[sub][x + t + 3];
    }
    g_tmp2[c * TMP_PLANE + (y + 29) * WW + x] = (a0 + a1) + (a2 + a3);
}

__global__ void conv_y_kernel() {   // grid = (12 ytile, 21 c), block = 96 (x)
    __shared__ float tap[76];       // 8 zeros | 60 taps | 8 zeros
    int c = blockIdx.y, y0 = blockIdx.x * 8, x = threadIdx.x;
    if (x < 76) tap[x] = (x >= 8 && x < 68) ? g_tap[x - 8] : 0.0f;
    __syncthreads();
    float acc[8];
#pragma unroll
    for (int i = 0; i < 8; i++) acc[i] = 0.0f;
    // tmpPad image row (y0-29+s) lives at storage row (y0+s)
    const float* tp = g_tmp2 + c * TMP_PLANE + y0 * WW + x;
#pragma unroll
    for (int s = 0; s < 67; s++) {
        float v = tp[s * WW];
#pragma unroll
        for (int i = 0; i < 8; i++) acc[i] += tap[s - i + 8] * v;
    }
#pragma unroll
    for (int i = 0; i < 8; i++)
        g_S[c * NN + (y0 + i) * WW + x] = acc[i];
}

// ---------------- fp8 GEMM: banded, 4-stage cp.async pipeline, m32 warp tiles ----------------
__device__ __forceinline__ void mma_fp8(float* d, uint32_t a0, uint32_t a1, uint32_t a2,
                                        uint32_t a3, uint32_t b0, uint32_t b1) {
    asm volatile(
        "mma.sync.aligned.m16n8k32.row.col.f32.e4m3.e4m3.f32 "
        "{%0,%1,%2,%3},{%4,%5,%6,%7},{%8,%9},{%0,%1,%2,%3};\n"
        : "+f"(d[0]), "+f"(d[1]), "+f"(d[2]), "+f"(d[3])
        : "r"(a0), "r"(a1), "r"(a2), "r"(a3), "r"(b0), "r"(b1));
}

__global__ void __launch_bounds__(128, 2) gemm_kernel() {
    // grid = (72, KSPLIT). Block: 128 rows; banded k-window split KSPLIT ways.
    __shared__ __align__(16) uint8_t sA[4 * SA_BUF];   // 65536 B
    __shared__ __align__(16) uint8_t sB[4 * SB_BUF];   // 24576 B
    int tid = threadIdx.x;
    int warp = tid >> 5, lane = tid & 31;
    int grp = lane >> 2, tig = lane & 3;
    int tile = blockIdx.x;
    int rowBase = tile * RB;

    int jlo, jhi;
    tile_window(tile, jlo, jhi);
    int len = jhi - jlo;
    int chunk = ((len / KSPLIT + KT - 1) / KT) * KT;
    int kstartRel = blockIdx.y * chunk;
    int kendRel = min(len, kstartRel + chunk);
    int NST = (kendRel > kstartRel) ? (kendRel - kstartRel) / KT : 0;

    const uint8_t* Arow0 = g_Kb + (size_t)rowBase * KB_W + kstartRel;
    const uint8_t* Bbase = g_pT8 + jlo + kstartRel;

    uint32_t sA_u = (uint32_t)__cvta_generic_to_shared(&sA[0]);
    uint32_t sB_u = (uint32_t)__cvta_generic_to_shared(&sB[0]);

    auto prefetch = [&](int s, int buf) {
        if (s >= NST) return;
        size_t kbase = (size_t)s * KT;
#pragma unroll
        for (int i = 0; i < 8; i++) {            // 1024 chunks of 16B for A (128 rows)
            int chunkid = tid + i * 128;
            int r = chunkid >> 3, c = chunkid & 7;
            const uint8_t* src = Arow0 + (size_t)r * KB_W + kbase + c * 16;
            uint32_t dst = sA_u + buf * SA_BUF + r * 128 + ((c ^ (r & 7)) << 4);
            CP_ASYNC16(dst, src);
        }
#pragma unroll
        for (int i = 0; i < 3; i++) {            // 384 chunks for B (48 rows)
            int chunkid = tid + i * 128;
            int r = chunkid >> 3, c = chunkid & 7;
            const uint8_t* src = Bbase + (size_t)r * NN + kbase + c * 16;
            uint32_t dst = sB_u + buf * SB_BUF + r * 128 + ((c ^ (r & 7)) << 4);
            CP_ASYNC16(dst, src);
        }
    };

    float d[2][6][4];
#pragma unroll
    for (int m = 0; m < 2; m++)
#pragma unroll
        for (int i = 0; i < 6; i++)
#pragma unroll
            for (int j = 0; j < 4; j++) d[m][i][j] = 0.0f;

    prefetch(0, 0); CP_COMMIT();
    prefetch(1, 1); CP_COMMIT();
    prefetch(2, 2); CP_COMMIT();

    // ---- ldmatrix address setup (loop-invariant) ----
    int l7 = lane & 7;
    int aHalf = lane >> 4;
    int bHalf = (lane >> 3) & 1;
    uint32_t aBase[2];
#pragma unroll
    for (int m = 0; m < 2; m++) {
        int aRow = warp * 32 + m * 16 + ((lane >> 3) & 1) * 8 + l7;
        aBase[m] = sA_u + (uint32_t)aRow * 128;
    }
    uint32_t bBase[3];
#pragma unroll
    for (int p = 0; p < 3; p++)
        bBase[p] = sB_u + (uint32_t)(((2 * p + (lane >> 4)) * 8 + l7) * 128);
    int offA[4], offB[4];
#pragma unroll
    for (int kk = 0; kk < 4; kk++) {
        offA[kk] = (((2 * kk + aHalf) ^ l7) << 4);
        offB[kk] = (((2 * kk + bHalf) ^ l7) << 4);
    }

    int buf = 0;
    for (int s = 0; s < NST; s++) {
        CP_WAIT2();
        __syncthreads();
        prefetch(s + 3, (s + 3) & 3);
        CP_COMMIT();
        uint32_t A0 = aBase[0] + buf * SA_BUF;
        uint32_t A1 = aBase[1] + buf * SA_BUF;
        uint32_t B0 = bBase[0] + buf * SB_BUF;
        uint32_t B1 = bBase[1] + buf * SB_BUF;
        uint32_t B2 = bBase[2] + buf * SB_BUF;
        buf = (buf + 1) & 3;
#pragma unroll
        for (int kk = 0; kk < 4; kk++) {
            uint32_t a00, a01, a02, a03, a10, a11, a12, a13;
            LDSM4(a00, a01, a02, a03, A0 + offA[kk]);
            LDSM4(a10, a11, a12, a13, A1 + offA[kk]);
            uint32_t b00, b01, b10, b11;
            LDSM4(b00, b01, b10, b11, B0 + offB[kk]);
            uint32_t b20, b21, b30, b31;
            LDSM4(b20, b21, b30, b31, B1 + offB[kk]);
            uint32_t b40, b41, b50, b51;
            LDSM4(b40, b41, b50, b51, B2 + offB[kk]);
            mma_fp8(d[0][0], a00, a01, a02, a03, b00, b01);
            mma_fp8(d[0][1], a00, a01, a02, a03, b10, b11);
            mma_fp8(d[0][2], a00, a01, a02, a03, b20, b21);
            mma_fp8(d[0][3], a00, a01, a02, a03, b30, b31);
            mma_fp8(d[0][4], a00, a01, a02, a03, b40, b41);
            mma_fp8(d[0][5], a00, a01, a02, a03, b50, b51);
            mma_fp8(d[1][0], a10, a11, a12, a13, b00, b01);
            mma_fp8(d[1][1], a10, a11, a12, a13, b10, b11);
            mma_fp8(d[1][2], a10, a11, a12, a13, b20, b21);
            mma_fp8(d[1][3], a10, a11, a12, a13, b30, b31);
            mma_fp8(d[1][4], a10, a11, a12, a13, b40, b41);
            mma_fp8(d[1][5], a10, a11, a12, a13, b50, b51);
        }
    }

    float* outp = g_Bp[blockIdx.y];
#pragma unroll
    for (int m = 0; m < 2; m++) {
        int row0 = rowBase + warp * 32 + m * 16 + grp;
#pragma unroll
        for (int nt = 0; nt < 3; nt++) {   // combine hi + lo/64
            int col = nt * 8 + 2 * tig;
            float v00 = d[m][nt][0] + d[m][nt + 3][0] * (1.0f / 64.0f);
            float v01 = d[m][nt][1] + d[m][nt + 3][1] * (1.0f / 64.0f);
            float v10 = d[m][nt][2] + d[m][nt + 3][2] * (1.0f / 64.0f);
            float v11 = d[m][nt][3] + d[m][nt + 3][3] * (1.0f / 64.0f);
            *reinterpret_cast<float2*>(&outp[(size_t)row0 * CP + col]) = make_float2(v00, v01);
            *reinterpret_cast<float2*>(&outp[(size_t)(row0 + 8) * CP + col]) = make_float2(v10, v11);
        }
    }
}

// ---------------- fused update + softmax: q = u - S@Ws^T - B@Wb^T, then probs ----------------
__global__ void update_kernel(const float* __restrict__ u, float* __restrict__ outp, int last) {
    __shared__ float su[128 * CC];
    __shared__ float sws[CC * CC], swb[CC * CC];
    int tid = threadIdx.x;
    for (int t = tid; t < CC * CC; t += 128) { sws[t] = g_Ws[t]; swb[t] = g_Wb[t]; }
    int base = blockIdx.x * 128 * CC;
    for (int t = tid; t < 128 * CC; t += 128) su[t] = u[base + t];
    __syncthreads();
    int n = blockIdx.x * 128 + tid;

    float sv[CC], bv[CP];
#pragma unroll
    for (int c = 0; c < CC; c++) sv[c] = g_S[c * NN + n];
#pragma unroll
    for (int q4 = 0; q4 < 6; q4++) {
        float4 a = *reinterpret_cast<const float4*>(&g_Bp[0][(size_t)n * CP + q4 * 4]);
        float4 b = *reinterpret_cast<const float4*>(&g_Bp[1][(size_t)n * CP + q4 * 4]);
        float4 cc4 = *reinterpret_cast<const float4*>(&g_Bp[2][(size_t)n * CP + q4 * 4]);
        float4 e = *reinterpret_cast<const float4*>(&g_Bp[3][(size_t)n * CP + q4 * 4]);
        bv[q4 * 4 + 0] = a.x + b.x + cc4.x + e.x;
        bv[q4 * 4 + 1] = a.y + b.y + cc4.y + e.y;
        bv[q4 * 4 + 2] = a.z + b.z + cc4.z + e.z;
        bv[q4 * 4 + 3] = a.w + b.w + cc4.w + e.w;
    }

    float qn[CC];
#pragma unroll
    for (int k = 0; k < CC; k++) {
        float acc = 0.0f;
#pragma unroll
        for (int c = 0; c < CC; c++)
            acc += sws[k * CC + c] * sv[c] + swb[k * CC + c] * bv[c];
        qn[k] = su[tid * CC + k] - acc;
    }

    if (last) {
#pragma unroll
        for (int k = 0; k < CC; k++) outp[n * CC + k] = qn[k];
    } else {
        emit_probs(qn, n);
    }
}

// ---------------- launch: build on main (no prep dep); prep+softmax0 on side ----------
extern "C" void kernel_launch(void* const* d_in, const int* in_sizes, int n_in,
                              void* d_out, int out_size) {
    const float* u   = (const float*)d_in[0];
    const float* ref = (const float*)d_in[1];
    const float* ws  = (const float*)d_in[2];
    const float* wb  = (const float*)d_in[3];
    const float* cm  = (const float*)d_in[4];
    float* out = (float*)d_out;

    static cudaStream_t s2 = nullptr;
    static cudaEvent_t eFork = nullptr, eEmit = nullptr, eConv = nullptr;
    if (s2 == nullptr) {
        cudaStreamCreateWithFlags(&s2, cudaStreamNonBlocking);
        cudaEventCreateWithFlags(&eFork, cudaEventDisableTiming);
        cudaEventCreateWithFlags(&eEmit, cudaEventDisableTiming);
        cudaEventCreateWithFlags(&eConv, cudaEventDisableTiming);
    }

    // fork side stream off the main (legacy) stream
    cudaEventRecord(eFork, 0);
    cudaStreamWaitEvent(s2, eFork, 0);

    // main: build_K immediately (reads ref directly; no prep dependency).
    build_k_kernel<<<dim3(12, 576), 128>>>(ref);

    // side: prep (taps, Ws/Wb, tmp halos) -> softmax0 -> convs (all in-order on s2)
    prep_kernel<<<36, 256, 0, s2>>>(ws, wb, cm);
    softmax0_kernel<<<72, 128, 0, s2>>>(u);
    cudaEventRecord(eEmit, s2);      // probs (and transitively prep) ready

    for (int it = 0; it < 5; it++) {
        if (it > 0) cudaStreamWaitEvent(s2, eEmit, 0);
        conv_x_kernel<<<dim3(96, 7), 288, 0, s2>>>();
        conv_y_kernel<<<dim3(12, 21), 96, 0, s2>>>();
        cudaEventRecord(eConv, s2);

        if (it == 0) cudaStreamWaitEvent(0, eEmit, 0);  // gemm needs softmax0
        gemm_kernel<<<dim3(NTILES, KSPLIT), 128>>>();

        cudaStreamWaitEvent(0, eConv, 0);                // update needs convs (and prep's Ws/Wb)
        update_kernel<<<72, 128>>>(u, out, it == 4 ? 1 : 0);
        if (it < 4) cudaEventRecord(eEmit, 0);           // new probs for next iter
    }
}